// round 13
// baseline (speedup 1.0000x reference)
#include <cuda_runtime.h>
#include <cuda_bf16.h>
#include <cstdint>
#include <math.h>

#define N_NODES 50000
#define NHALF   25024          // encoder half-split (multiple of 64 and 8)
#define E_EDGES 800000
#define F_IN    128
#define HID     96
#define L_LAYERS 4
#define NQ      4
#define FULLM 0xffffffffu

// quarter boundaries (multiples of 64)
__constant__ int c_qb[NQ + 1] = {0, 12544, 25088, 37632, 50000};
static const int h_qb[NQ + 1] = {0, 12544, 25088, 37632, 50000};

// ---------------- device scratch ----------------
__device__ __align__(16) float g_h    [N_NODES * HID];
__device__ __align__(16) float g_hn   [N_NODES * HID];
__device__ __align__(16) float g_xlxr0[N_NODES * 2 * HID];  // ping
__device__ __align__(16) float g_xlxr1[N_NODES * 2 * HID];  // pong
__device__ __align__(16) int   g_cnt   [N_NODES];
__device__ __align__(16) int   g_rowptr[N_NODES + 1];
__device__ __align__(16) int   g_cursor[N_NODES];
__device__ __align__(16) int2  g_edge  [E_EDGES];   // (src, ew bits), sorted by dst
__device__ int g_is64;

// bf16 weight images, n-major [CW][K]: enc 96x128 @0; layer i 192x96 @ 12288 + i*18432
#define BW_ENC_OFF 0
#define BW_LAY_OFF 12288
#define BW_TOTAL   (12288 + 4 * 18432)
__device__ __align__(16) unsigned short g_bw_hi[BW_TOTAL];
__device__ __align__(16) unsigned short g_bw_lo[BW_TOTAL];

// ---------------- edge_index dtype sniff ----------------
__global__ void detect_kernel(const int* ei32) {
    bool is64 = true;
    #pragma unroll
    for (int i = 0; i < 8; i++) if (ei32[2 * i + 1] != 0) is64 = false;
    g_is64 = is64 ? 1 : 0;
}

__device__ __forceinline__ void load_edge(const void* ei, int e, int& s, int& d) {
    if (g_is64) {
        const long long* p = (const long long*)ei;
        s = (int)p[e]; d = (int)p[E_EDGES + e];
    } else {
        const int* p = (const int*)ei;
        s = p[e]; d = p[E_EDGES + e];
    }
}

// ---------------- CSR build ----------------
__global__ void __launch_bounds__(256) hist_kernel(const void* ei) {
    int base = (blockIdx.x * blockDim.x + threadIdx.x) * 2;
    #pragma unroll
    for (int i = 0; i < 2; i++) {
        int e = base + i;
        if (e < E_EDGES) {
            int s, d; load_edge(ei, e, s, d);
            atomicAdd(&g_cnt[d], 1);
        }
    }
}

__global__ void __launch_bounds__(1024) scan_kernel() {
    __shared__ int ps[1024];
    int t = threadIdx.x;
    const int CH = (N_NODES + 1023) / 1024;
    int base = t * CH;
    int sum = 0;
    for (int i = 0; i < CH; i++) {
        int idx = base + i;
        if (idx < N_NODES) sum += g_cnt[idx];
    }
    ps[t] = sum;
    __syncthreads();
    for (int off = 1; off < 1024; off <<= 1) {
        int v = (t >= off) ? ps[t - off] : 0;
        __syncthreads();
        ps[t] += v;
        __syncthreads();
    }
    int run = ps[t] - sum;
    for (int i = 0; i < CH; i++) {
        int idx = base + i;
        if (idx < N_NODES) {
            g_rowptr[idx] = run;
            g_cursor[idx] = run;
            run += g_cnt[idx];
        }
    }
    if (t == 0) g_rowptr[N_NODES] = E_EDGES;
}

__global__ void __launch_bounds__(256) scatter_kernel(const void* ei, const float* __restrict__ ew) {
    int base = (blockIdx.x * blockDim.x + threadIdx.x) * 2;
    #pragma unroll
    for (int i = 0; i < 2; i++) {
        int e = base + i;
        if (e < E_EDGES) {
            int s, d; load_edge(ei, e, s, d);
            int p = atomicAdd(&g_cursor[d], 1);
            g_edge[p] = make_int2(s, __float_as_int(ew[e]));
        }
    }
}

// ---------------- prep: transpose + bf16-split weights into n-major images ----------------
__global__ void __launch_bounds__(256) prep_w_kernel(
    const float* __restrict__ encW, const float* __restrict__ Wl, const float* __restrict__ Wr)
{
    int idx = blockIdx.x * blockDim.x + threadIdx.x;
    if (idx >= BW_TOTAL) return;
    float v; int dest;
    if (idx < 12288) {                 // enc: [96][128]
        int n = idx >> 7, k = idx & 127;
        v = encW[k * HID + n];
        dest = n * 128 + k;
    } else {
        int r = idx - 12288;
        int i = r / 18432; r -= i * 18432;
        int n = r / HID, k = r % HID;  // [192][96]
        v = (n < HID) ? Wl[(size_t)i * HID * HID + k * HID + n]
                      : Wr[(size_t)i * HID * HID + k * HID + (n - HID)];
        dest = BW_LAY_OFF + i * 18432 + n * HID + k;
    }
    __nv_bfloat16 hi = __float2bfloat16(v);
    float lof = v - __bfloat162float(hi);
    __nv_bfloat16 lo = __float2bfloat16(lof);
    g_bw_hi[dest] = *(unsigned short*)&hi;
    g_bw_lo[dest] = *(unsigned short*)&lo;
}

// ---------------- tensor-core GEMM via mma.sync (R11-proven) ----------------
__device__ __forceinline__ void mma16816(
    float& c0, float& c1, float& c2, float& c3,
    uint32_t a0, uint32_t a1, uint32_t a2, uint32_t a3,
    uint32_t b0, uint32_t b1)
{
    asm volatile(
        "mma.sync.aligned.m16n8k16.row.col.f32.bf16.bf16.f32 "
        "{%0,%1,%2,%3}, {%4,%5,%6,%7}, {%8,%9}, {%0,%1,%2,%3};"
        : "+f"(c0), "+f"(c1), "+f"(c2), "+f"(c3)
        : "r"(a0), "r"(a1), "r"(a2), "r"(a3), "r"(b0), "r"(b1));
}

template <int K, int CW, int CW1, int WN>
__global__ void __launch_bounds__(256) gemm_mma_kernel(
    const float* __restrict__ A,
    const unsigned short* __restrict__ Bhi, const unsigned short* __restrict__ Blo,
    const float* __restrict__ b1v, const float* __restrict__ b2v,
    float* __restrict__ C, int rbeg, int rend)
{
    constexpr int NS  = K / 16;
    constexpr int NF  = WN / 8;
    constexpr int SWD = K / 2 + 4;

    __shared__ uint32_t Ah[64 * SWD];
    __shared__ uint32_t Al[64 * SWD];

    const int tid  = threadIdx.x;
    const int wid  = tid >> 5;
    const int lane = tid & 31;
    const int g    = lane >> 2;
    const int t    = lane & 3;
    const int warp_m = wid >> 2;
    const int warp_n = wid & 3;
    const int rowbase = rbeg + blockIdx.x * 64;

    for (int i = tid; i < 64 * (K / 4); i += 256) {
        int row = i / (K / 4);
        int kq  = (i % (K / 4)) * 4;
        float4 v = make_float4(0.f, 0.f, 0.f, 0.f);
        int grow = rowbase + row;
        if (grow < rend) v = *(const float4*)(A + (size_t)grow * K + kq);
        __nv_bfloat162 h01 = __floats2bfloat162_rn(v.x, v.y);
        __nv_bfloat162 h23 = __floats2bfloat162_rn(v.z, v.w);
        __nv_bfloat162 l01 = __floats2bfloat162_rn(v.x - __bfloat162float(h01.x),
                                                   v.y - __bfloat162float(h01.y));
        __nv_bfloat162 l23 = __floats2bfloat162_rn(v.z - __bfloat162float(h23.x),
                                                   v.w - __bfloat162float(h23.y));
        int base = row * SWD + (kq >> 1);
        Ah[base]     = *(uint32_t*)&h01;
        Ah[base + 1] = *(uint32_t*)&h23;
        Al[base]     = *(uint32_t*)&l01;
        Al[base + 1] = *(uint32_t*)&l23;
    }
    __syncthreads();

    const uint32_t* BwH = (const uint32_t*)Bhi;
    const uint32_t* BwL = (const uint32_t*)Blo;

    float c[2][NF][4];
    #pragma unroll
    for (int mf = 0; mf < 2; mf++)
        #pragma unroll
        for (int nf = 0; nf < NF; nf++)
            #pragma unroll
            for (int q = 0; q < 4; q++) c[mf][nf][q] = 0.f;

    #pragma unroll
    for (int s = 0; s < 3; s++) {
        const uint32_t* Aimg = (s < 2) ? Ah : Al;
        const uint32_t* Bimg = (s == 1) ? BwL : BwH;
        #pragma unroll
        for (int ks = 0; ks < NS; ks++) {
            uint32_t a[2][4];
            #pragma unroll
            for (int mf = 0; mf < 2; mf++) {
                int r0 = warp_m * 32 + mf * 16 + g;
                int wi = r0 * SWD + ks * 8 + t;
                a[mf][0] = Aimg[wi];
                a[mf][1] = Aimg[wi + 8 * SWD];
                a[mf][2] = Aimg[wi + 4];
                a[mf][3] = Aimg[wi + 8 * SWD + 4];
            }
            #pragma unroll
            for (int nf = 0; nf < NF; nf++) {
                int n = warp_n * WN + nf * 8 + g;
                int bw = n * (K / 2) + ks * 8 + t;
                uint32_t b0 = __ldg(&Bimg[bw]);
                uint32_t b1 = __ldg(&Bimg[bw + 4]);
                #pragma unroll
                for (int mf = 0; mf < 2; mf++)
                    mma16816(c[mf][nf][0], c[mf][nf][1], c[mf][nf][2], c[mf][nf][3],
                             a[mf][0], a[mf][1], a[mf][2], a[mf][3], b0, b1);
            }
        }
    }

    #pragma unroll
    for (int nf = 0; nf < NF; nf++) {
        int col = warp_n * WN + nf * 8 + 2 * t;
        float bv0 = (col < CW1) ? b1v[col] : b2v[col - CW1];
        float bv1 = (col + 1 < CW1) ? b1v[col + 1] : b2v[col + 1 - CW1];
        #pragma unroll
        for (int mf = 0; mf < 2; mf++) {
            int row = rowbase + warp_m * 32 + mf * 16 + g;
            if (row < rend)
                *(float2*)(C + (size_t)row * CW + col) =
                    make_float2(c[mf][nf][0] + bv0, c[mf][nf][1] + bv1);
            if (row + 8 < rend)
                *(float2*)(C + (size_t)(row + 8) * CW + col) =
                    make_float2(c[mf][nf][2] + bv0, c[mf][nf][3] + bv1);
        }
    }
}

// ---------------- warp reduce ----------------
__device__ __forceinline__ float wsum(float v) {
    #pragma unroll
    for (int o = 16; o > 0; o >>= 1) v += __shfl_xor_sync(FULLM, v, o);
    return v;
}
__device__ __forceinline__ float wmax(float v) {
    #pragma unroll
    for (int o = 16; o > 0; o >>= 1) v = fmaxf(v, __shfl_xor_sync(FULLM, v, o));
    return v;
}

// ---------------- initial LayerNorm + ReLU (h -> hn), range-parameterized ----------------
__global__ void __launch_bounds__(256) ln_init_kernel(
    const float* __restrict__ h,
    const float* __restrict__ g, const float* __restrict__ b,
    float* __restrict__ hn, int nbeg, int nend)
{
    int warp = threadIdx.x >> 5;
    int lane = threadIdx.x & 31;
    int n = nbeg + blockIdx.x * 8 + warp;
    if (n >= nend) return;
    size_t base = (size_t)n * HID;

    float v0 = h[base + lane], v1 = h[base + lane + 32], v2 = h[base + lane + 64];
    float mean = wsum(v0 + v1 + v2) * (1.0f / HID);
    float d0 = v0 - mean, d1 = v1 - mean, d2 = v2 - mean;
    float rstd = rsqrtf(wsum(fmaf(d0, d0, fmaf(d1, d1, d2 * d2))) * (1.0f / HID) + 1e-5f);
    hn[base + lane]      = fmaxf(fmaf(d0 * rstd, g[lane],      b[lane]),      0.f);
    hn[base + lane + 32] = fmaxf(fmaf(d1 * rstd, g[lane + 32], b[lane + 32]), 0.f);
    hn[base + lane + 64] = fmaxf(fmaf(d2 * rstd, g[lane + 64], b[lane + 64]), 0.f);
}

// ---------------- fused GAT layer (R11-proven scalar body) ----------------
__global__ void __launch_bounds__(256) gat_fused_kernel(
    const float* __restrict__ xlxr,
    const float* __restrict__ We,  const float* __restrict__ att,
    const float* __restrict__ bias,
    const float* __restrict__ lg,  const float* __restrict__ lb,
    int nbeg, int nend)
{
    __shared__ float sWe[HID], sAtt[HID], sBias[HID], sG[HID], sB[HID];
    int t = threadIdx.x;
    if (t < HID) {
        sWe[t] = We[t]; sAtt[t] = att[t]; sBias[t] = bias[t];
        sG[t] = lg[t];  sB[t]  = lb[t];
    }
    __syncthreads();

    int warp = t >> 5, lane = t & 31;
    int n = nbeg + blockIdx.x * 8 + warp;
    if (n >= nend) return;

    int r0 = g_rowptr[n], r1 = g_rowptr[n + 1];
    const float* xrp = xlxr + (size_t)n * 192 + 96;
    float xr0 = xrp[lane], xr1 = xrp[lane + 32], xr2 = xrp[lane + 64];
    float we0 = sWe[lane],  we1 = sWe[lane + 32],  we2 = sWe[lane + 64];
    float at0 = sAtt[lane], at1 = sAtt[lane + 32], at2 = sAtt[lane + 64];

    float m = -INFINITY, ssum = 0.f;
    float a0 = 0.f, a1 = 0.f, a2 = 0.f;

    for (int c0 = r0; c0 < r1; c0 += 32) {
        int cnt = min(32, r1 - c0);
        int p = c0 + lane;
        int   si = 0;
        float wE = 0.f;
        if (lane < cnt) {
            int2 ed = g_edge[p];
            si = ed.x;
            wE = __int_as_float(ed.y);
        }

        // ---- pass A: alpha per edge (coalesced row loads, independent reduces)
        float myal = -INFINITY;
        int j = 0;
        for (; j + 2 <= cnt; j += 2) {
            int   sa = __shfl_sync(FULLM, si, j);
            int   sb = __shfl_sync(FULLM, si, j + 1);
            float wa = __shfl_sync(FULLM, wE, j);
            float wb = __shfl_sync(FULLM, wE, j + 1);
            const float* xa = xlxr + (size_t)sa * 192;
            const float* xb = xlxr + (size_t)sb * 192;
            float xa0 = xa[lane], xa1 = xa[lane + 32], xa2 = xa[lane + 64];
            float xb0 = xb[lane], xb1 = xb[lane + 32], xb2 = xb[lane + 64];

            float e0 = xa0 + xr0 + wa * we0; e0 = e0 > 0.f ? e0 : 0.2f * e0;
            float e1 = xa1 + xr1 + wa * we1; e1 = e1 > 0.f ? e1 : 0.2f * e1;
            float e2 = xa2 + xr2 + wa * we2; e2 = e2 > 0.f ? e2 : 0.2f * e2;
            float ta = fmaf(e0, at0, fmaf(e1, at1, e2 * at2));

            float f0 = xb0 + xr0 + wb * we0; f0 = f0 > 0.f ? f0 : 0.2f * f0;
            float f1 = xb1 + xr1 + wb * we1; f1 = f1 > 0.f ? f1 : 0.2f * f1;
            float f2 = xb2 + xr2 + wb * we2; f2 = f2 > 0.f ? f2 : 0.2f * f2;
            float tb = fmaf(f0, at0, fmaf(f1, at1, f2 * at2));

            #pragma unroll
            for (int o = 16; o > 0; o >>= 1) {
                ta += __shfl_xor_sync(FULLM, ta, o);
                tb += __shfl_xor_sync(FULLM, tb, o);
            }
            myal = (lane == j)     ? ta : myal;
            myal = (lane == j + 1) ? tb : myal;
        }
        if (j < cnt) {
            int   sa = __shfl_sync(FULLM, si, j);
            float wa = __shfl_sync(FULLM, wE, j);
            const float* xa = xlxr + (size_t)sa * 192;
            float xa0 = xa[lane], xa1 = xa[lane + 32], xa2 = xa[lane + 64];
            float e0 = xa0 + xr0 + wa * we0; e0 = e0 > 0.f ? e0 : 0.2f * e0;
            float e1 = xa1 + xr1 + wa * we1; e1 = e1 > 0.f ? e1 : 0.2f * e1;
            float e2 = xa2 + xr2 + wa * we2; e2 = e2 > 0.f ? e2 : 0.2f * e2;
            float ta = fmaf(e0, at0, fmaf(e1, at1, e2 * at2));
            #pragma unroll
            for (int o = 16; o > 0; o >>= 1) ta += __shfl_xor_sync(FULLM, ta, o);
            myal = (lane == j) ? ta : myal;
        }

        // ---- chunk-level online softmax merge
        float cm = wmax(myal);
        float nm = fmaxf(m, cm);
        float corr = __expf(m - nm);
        ssum *= corr; a0 *= corr; a1 *= corr; a2 *= corr;
        float wexp = (lane < cnt) ? __expf(myal - nm) : 0.f;
        ssum += wsum(wexp);
        m = nm;

        // ---- pass B: aggregation (rows L1-hot from pass A)
        int jj = 0;
        for (; jj + 4 <= cnt; jj += 4) {
            float w0 = __shfl_sync(FULLM, wexp, jj + 0);
            float w1 = __shfl_sync(FULLM, wexp, jj + 1);
            float w2 = __shfl_sync(FULLM, wexp, jj + 2);
            float w3 = __shfl_sync(FULLM, wexp, jj + 3);
            const float* x0p = xlxr + (size_t)__shfl_sync(FULLM, si, jj + 0) * 192;
            const float* x1p = xlxr + (size_t)__shfl_sync(FULLM, si, jj + 1) * 192;
            const float* x2p = xlxr + (size_t)__shfl_sync(FULLM, si, jj + 2) * 192;
            const float* x3p = xlxr + (size_t)__shfl_sync(FULLM, si, jj + 3) * 192;
            float v00 = x0p[lane], v01 = x0p[lane + 32], v02 = x0p[lane + 64];
            float v10 = x1p[lane], v11 = x1p[lane + 32], v12 = x1p[lane + 64];
            float v20 = x2p[lane], v21 = x2p[lane + 32], v22 = x2p[lane + 64];
            float v30 = x3p[lane], v31 = x3p[lane + 32], v32 = x3p[lane + 64];
            a0 = fmaf(w0, v00, a0); a1 = fmaf(w0, v01, a1); a2 = fmaf(w0, v02, a2);
            a0 = fmaf(w1, v10, a0); a1 = fmaf(w1, v11, a1); a2 = fmaf(w1, v12, a2);
            a0 = fmaf(w2, v20, a0); a1 = fmaf(w2, v21, a1); a2 = fmaf(w2, v22, a2);
            a0 = fmaf(w3, v30, a0); a1 = fmaf(w3, v31, a1); a2 = fmaf(w3, v32, a2);
        }
        for (; jj < cnt; jj++) {
            float w = __shfl_sync(FULLM, wexp, jj);
            const float* xp = xlxr + (size_t)__shfl_sync(FULLM, si, jj) * 192;
            a0 = fmaf(w, xp[lane],      a0);
            a1 = fmaf(w, xp[lane + 32], a1);
            a2 = fmaf(w, xp[lane + 64], a2);
        }
    }

    float inv = 1.0f / (ssum + 1e-16f);
    a0 *= inv; a1 *= inv; a2 *= inv;

    // ---- residual + bias + LayerNorm + ReLU
    size_t base = (size_t)n * HID;
    float x0 = g_h[base + lane]      + a0 + sBias[lane];
    float x1 = g_h[base + lane + 32] + a1 + sBias[lane + 32];
    float x2 = g_h[base + lane + 64] + a2 + sBias[lane + 64];
    g_h[base + lane]      = x0;
    g_h[base + lane + 32] = x1;
    g_h[base + lane + 64] = x2;

    float mean = wsum(x0 + x1 + x2) * (1.0f / HID);
    float d0 = x0 - mean, d1 = x1 - mean, d2 = x2 - mean;
    float rstd = rsqrtf(wsum(fmaf(d0, d0, fmaf(d1, d1, d2 * d2))) * (1.0f / HID) + 1e-5f);
    g_hn[base + lane]      = fmaxf(fmaf(d0 * rstd, sG[lane],      sB[lane]),      0.f);
    g_hn[base + lane + 32] = fmaxf(fmaf(d1 * rstd, sG[lane + 32], sB[lane + 32]), 0.f);
    g_hn[base + lane + 64] = fmaxf(fmaf(d2 * rstd, sG[lane + 64], sB[lane + 64]), 0.f);
}

// ---------------- final FC ----------------
__global__ void __launch_bounds__(256) fc_kernel(
    const float* __restrict__ fcW, const float* __restrict__ fcb,
    float* __restrict__ out)
{
    int warp = threadIdx.x >> 5;
    int lane = threadIdx.x & 31;
    int n = blockIdx.x * 8 + warp;
    if (n >= N_NODES) return;
    size_t base = (size_t)n * HID;
    float acc = fmaf(g_hn[base + lane], fcW[lane],
                fmaf(g_hn[base + lane + 32], fcW[lane + 32],
                     g_hn[base + lane + 64] * fcW[lane + 64]));
    acc = wsum(acc);
    if (lane == 0) out[n] = acc + fcb[0];
}

// ---------------- launch ----------------
extern "C" void kernel_launch(void* const* d_in, const int* in_sizes, int n_in,
                              void* d_out, int out_size)
{
    const float* x    = (const float*)d_in[0];
    const void*  ei   = (const void*) d_in[1];
    const float* ew   = (const float*)d_in[2];
    const float* encW = (const float*)d_in[3];
    const float* encb = (const float*)d_in[4];
    const float* Wl   = (const float*)d_in[5];
    const float* bl   = (const float*)d_in[6];
    const float* Wr   = (const float*)d_in[7];
    const float* br   = (const float*)d_in[8];
    const float* We   = (const float*)d_in[9];
    const float* att  = (const float*)d_in[10];
    const float* bias = (const float*)d_in[11];
    const float* lng  = (const float*)d_in[12];
    const float* lnb  = (const float*)d_in[13];
    const float* lnfg = (const float*)d_in[14];
    const float* lnfb = (const float*)d_in[15];
    const float* fcW  = (const float*)d_in[16];
    const float* fcb  = (const float*)d_in[17];
    float*       out  = (float*)d_out;

    void *p_h, *p_hn, *p_cnt, *p_x0, *p_x1, *p_bh, *p_bl;
    cudaGetSymbolAddress(&p_h,   g_h);
    cudaGetSymbolAddress(&p_hn,  g_hn);
    cudaGetSymbolAddress(&p_cnt, g_cnt);
    cudaGetSymbolAddress(&p_x0,  g_xlxr0);
    cudaGetSymbolAddress(&p_x1,  g_xlxr1);
    cudaGetSymbolAddress(&p_bh,  g_bw_hi);
    cudaGetSymbolAddress(&p_bl,  g_bw_lo);
    float* hbuf  = (float*)p_h;
    float* hnbuf = (float*)p_hn;
    float* xbuf[2] = { (float*)p_x0, (float*)p_x1 };
    const unsigned short* bwh = (const unsigned short*)p_bh;
    const unsigned short* bwl = (const unsigned short*)p_bl;

    const int GEMM_A = NHALF / 64;
    const int GEMM_B = (N_NODES - NHALF + 63) / 64;
    const int NODE_A = NHALF / 8;
    const int NODE_B = (N_NODES - NHALF + 7) / 8;
    const int node_blocks  = (N_NODES + 7) / 8;
    const int edge2_blocks = (E_EDGES / 2 + 255) / 256;
    const int prep_blocks  = (BW_TOTAL + 255) / 256;

    cudaStream_t s2, s3;
    cudaStreamCreateWithFlags(&s2, cudaStreamNonBlocking);
    cudaStreamCreateWithFlags(&s3, cudaStreamNonBlocking);
    cudaEvent_t evFork, evCSR, evEncA, evG0, evGfull[L_LAYERS];
    cudaEvent_t evQ[L_LAYERS][NQ];
    cudaEventCreateWithFlags(&evFork, cudaEventDisableTiming);
    cudaEventCreateWithFlags(&evCSR,  cudaEventDisableTiming);
    cudaEventCreateWithFlags(&evEncA, cudaEventDisableTiming);
    cudaEventCreateWithFlags(&evG0,   cudaEventDisableTiming);
    for (int i = 0; i < L_LAYERS; i++) {
        cudaEventCreateWithFlags(&evGfull[i], cudaEventDisableTiming);
        for (int q = 0; q < NQ; q++)
            cudaEventCreateWithFlags(&evQ[i][q], cudaEventDisableTiming);
    }

    cudaEventRecord(evFork, 0);
    cudaStreamWaitEvent(s2, evFork, 0);
    cudaStreamWaitEvent(s3, evFork, 0);

    // ---- s2: CSR build ----
    detect_kernel<<<1, 1, 0, s2>>>((const int*)ei);
    cudaMemsetAsync(p_cnt, 0, N_NODES * sizeof(int), s2);
    hist_kernel<<<edge2_blocks, 256, 0, s2>>>(ei);
    scan_kernel<<<1, 1024, 0, s2>>>();
    scatter_kernel<<<edge2_blocks, 256, 0, s2>>>(ei, ew);
    cudaEventRecord(evCSR, s2);

    // ---- main: weight prep, then encoder (half-split, R10/R11-proven) ----
    prep_w_kernel<<<prep_blocks, 256>>>(encW, Wl, Wr);
    gemm_mma_kernel<F_IN, HID, HID, 24><<<GEMM_A, 256>>>(
        x, bwh + BW_ENC_OFF, bwl + BW_ENC_OFF, encb, encb, hbuf, 0, NHALF);
    cudaEventRecord(evEncA, 0);

    cudaStreamWaitEvent(s3, evEncA, 0);
    ln_init_kernel<<<NODE_A, 256, 0, s3>>>(hbuf, lng, lnb, hnbuf, 0, NHALF);
    gemm_mma_kernel<HID, 2 * HID, HID, 48><<<GEMM_A, 256, 0, s3>>>(
        hnbuf, bwh + BW_LAY_OFF, bwl + BW_LAY_OFF, bl, br, xbuf[0], 0, NHALF);
    cudaEventRecord(evG0, s3);

    gemm_mma_kernel<F_IN, HID, HID, 24><<<GEMM_B, 256>>>(
        x, bwh + BW_ENC_OFF, bwl + BW_ENC_OFF, encb, encb, hbuf, NHALF, N_NODES);
    ln_init_kernel<<<NODE_B, 256>>>(hbuf, lng, lnb, hnbuf, NHALF, N_NODES);
    gemm_mma_kernel<HID, 2 * HID, HID, 48><<<GEMM_B, 256>>>(
        hnbuf, bwh + BW_LAY_OFF, bwl + BW_LAY_OFF, bl, br, xbuf[0], NHALF, N_NODES);

    cudaStreamWaitEvent(0, evG0, 0);
    cudaStreamWaitEvent(0, evCSR, 0);

    // ---- quarter-pipelined layer loop ----
    for (int i = 0; i < L_LAYERS; i++) {
        const float* gnext = (i < L_LAYERS - 1) ? (lng + (i + 1) * HID) : lnfg;
        const float* bnext = (i < L_LAYERS - 1) ? (lnb + (i + 1) * HID) : lnfb;
        float* xb_cur = xbuf[i & 1];
        float* xb_nxt = xbuf[(i + 1) & 1];

        for (int q = 0; q < NQ; q++) {
            int nb = h_qb[q], ne = h_qb[q + 1];
            int nodeq = (ne - nb + 7) / 8;
            gat_fused_kernel<<<nodeq, 256>>>(
                xb_cur, We + i * HID, att + i * HID, bias + i * HID, gnext, bnext,
                nb, ne);
            if (i + 1 < L_LAYERS) {
                cudaEventRecord(evQ[i][q], 0);
                // s3: gemm(i+1) for this quarter as soon as its hn rows exist
                cudaStreamWaitEvent(s3, evQ[i][q], 0);
                int gq = (ne - nb + 63) / 64;
                gemm_mma_kernel<HID, 2 * HID, HID, 48><<<gq, 256, 0, s3>>>(
                    hnbuf,
                    bwh + BW_LAY_OFF + (i + 1) * 18432, bwl + BW_LAY_OFF + (i + 1) * 18432,
                    bl + (i + 1) * HID, br + (i + 1) * HID, xb_nxt, nb, ne);
            }
        }
        if (i + 1 < L_LAYERS) {
            cudaEventRecord(evGfull[i], s3);
            cudaStreamWaitEvent(0, evGfull[i], 0);   // gat(i+1) needs full gemm(i+1)
        }
    }

    fc_kernel<<<node_blocks, 256>>>(fcW, fcb, out);

    cudaEventDestroy(evFork);
    cudaEventDestroy(evCSR);
    cudaEventDestroy(evEncA);
    cudaEventDestroy(evG0);
    for (int i = 0; i < L_LAYERS; i++) {
        cudaEventDestroy(evGfull[i]);
        for (int q = 0; q < NQ; q++) cudaEventDestroy(evQ[i][q]);
    }
    cudaStreamDestroy(s2);
    cudaStreamDestroy(s3);
}

// round 14
// speedup vs baseline: 1.1295x; 1.1295x over previous
#include <cuda_runtime.h>
#include <cuda_bf16.h>
#include <cstdint>
#include <math.h>

#define N_NODES 50000
#define NHALF   25024          // multiple of 64 and 8
#define E_EDGES 800000
#define F_IN    128
#define HID     96
#define L_LAYERS 4
#define FULLM 0xffffffffu

// ---------------- device scratch ----------------
__device__ __align__(16) float g_h    [N_NODES * HID];
__device__ __align__(16) float g_hn   [N_NODES * HID];
__device__ __align__(16) float g_xlxr0[N_NODES * 2 * HID];  // ping
__device__ __align__(16) float g_xlxr1[N_NODES * 2 * HID];  // pong
__device__ __align__(16) int   g_cnt   [N_NODES];
__device__ __align__(16) int   g_rowptr[N_NODES + 1];
__device__ __align__(16) int   g_cursor[N_NODES];
__device__ __align__(16) int2  g_edge  [E_EDGES];   // (src, ew bits), sorted by dst
__device__ int g_is64;

// bf16 weight images, n-major [CW][K]: enc 96x128 @0; layer i 192x96 @ 12288 + i*18432
#define BW_ENC_OFF 0
#define BW_LAY_OFF 12288
#define BW_TOTAL   (12288 + 4 * 18432)
__device__ __align__(16) unsigned short g_bw_hi[BW_TOTAL];
__device__ __align__(16) unsigned short g_bw_lo[BW_TOTAL];

// ---------------- edge_index dtype sniff ----------------
__global__ void detect_kernel(const int* ei32) {
    bool is64 = true;
    #pragma unroll
    for (int i = 0; i < 8; i++) if (ei32[2 * i + 1] != 0) is64 = false;
    g_is64 = is64 ? 1 : 0;
}

__device__ __forceinline__ void load_edge(const void* ei, int e, int& s, int& d) {
    if (g_is64) {
        const long long* p = (const long long*)ei;
        s = (int)p[e]; d = (int)p[E_EDGES + e];
    } else {
        const int* p = (const int*)ei;
        s = p[e]; d = p[E_EDGES + e];
    }
}

// ---------------- CSR build ----------------
__global__ void __launch_bounds__(256) hist_kernel(const void* ei) {
    int base = (blockIdx.x * blockDim.x + threadIdx.x) * 2;
    #pragma unroll
    for (int i = 0; i < 2; i++) {
        int e = base + i;
        if (e < E_EDGES) {
            int s, d; load_edge(ei, e, s, d);
            atomicAdd(&g_cnt[d], 1);
        }
    }
}

__global__ void __launch_bounds__(1024) scan_kernel() {
    __shared__ int ps[1024];
    int t = threadIdx.x;
    const int CH = (N_NODES + 1023) / 1024;
    int base = t * CH;
    int sum = 0;
    for (int i = 0; i < CH; i++) {
        int idx = base + i;
        if (idx < N_NODES) sum += g_cnt[idx];
    }
    ps[t] = sum;
    __syncthreads();
    for (int off = 1; off < 1024; off <<= 1) {
        int v = (t >= off) ? ps[t - off] : 0;
        __syncthreads();
        ps[t] += v;
        __syncthreads();
    }
    int run = ps[t] - sum;
    for (int i = 0; i < CH; i++) {
        int idx = base + i;
        if (idx < N_NODES) {
            g_rowptr[idx] = run;
            g_cursor[idx] = run;
            run += g_cnt[idx];
        }
    }
    if (t == 0) g_rowptr[N_NODES] = E_EDGES;
}

__global__ void __launch_bounds__(256) scatter_kernel(const void* ei, const float* __restrict__ ew) {
    int base = (blockIdx.x * blockDim.x + threadIdx.x) * 2;
    #pragma unroll
    for (int i = 0; i < 2; i++) {
        int e = base + i;
        if (e < E_EDGES) {
            int s, d; load_edge(ei, e, s, d);
            int p = atomicAdd(&g_cursor[d], 1);
            g_edge[p] = make_int2(s, __float_as_int(ew[e]));
        }
    }
}

// ---------------- prep: transpose + bf16-split weights into n-major images ----------------
__global__ void __launch_bounds__(256) prep_w_kernel(
    const float* __restrict__ encW, const float* __restrict__ Wl, const float* __restrict__ Wr)
{
    int idx = blockIdx.x * blockDim.x + threadIdx.x;
    if (idx >= BW_TOTAL) return;
    float v; int dest;
    if (idx < 12288) {                 // enc: [96][128]
        int n = idx >> 7, k = idx & 127;
        v = encW[k * HID + n];
        dest = n * 128 + k;
    } else {
        int r = idx - 12288;
        int i = r / 18432; r -= i * 18432;
        int n = r / HID, k = r % HID;  // [192][96]
        v = (n < HID) ? Wl[(size_t)i * HID * HID + k * HID + n]
                      : Wr[(size_t)i * HID * HID + k * HID + (n - HID)];
        dest = BW_LAY_OFF + i * 18432 + n * HID + k;
    }
    __nv_bfloat16 hi = __float2bfloat16(v);
    float lof = v - __bfloat162float(hi);
    __nv_bfloat16 lo = __float2bfloat16(lof);
    g_bw_hi[dest] = *(unsigned short*)&hi;
    g_bw_lo[dest] = *(unsigned short*)&lo;
}

// ---------------- tensor-core GEMM via mma.sync (R11-proven) ----------------
__device__ __forceinline__ void mma16816(
    float& c0, float& c1, float& c2, float& c3,
    uint32_t a0, uint32_t a1, uint32_t a2, uint32_t a3,
    uint32_t b0, uint32_t b1)
{
    asm volatile(
        "mma.sync.aligned.m16n8k16.row.col.f32.bf16.bf16.f32 "
        "{%0,%1,%2,%3}, {%4,%5,%6,%7}, {%8,%9}, {%0,%1,%2,%3};"
        : "+f"(c0), "+f"(c1), "+f"(c2), "+f"(c3)
        : "r"(a0), "r"(a1), "r"(a2), "r"(a3), "r"(b0), "r"(b1));
}

template <int K, int CW, int CW1, int WN>
__global__ void __launch_bounds__(256) gemm_mma_kernel(
    const float* __restrict__ A,
    const unsigned short* __restrict__ Bhi, const unsigned short* __restrict__ Blo,
    const float* __restrict__ b1v, const float* __restrict__ b2v,
    float* __restrict__ C, int rbeg, int rend)
{
    constexpr int NS  = K / 16;
    constexpr int NF  = WN / 8;
    constexpr int SWD = K / 2 + 4;

    __shared__ uint32_t Ah[64 * SWD];
    __shared__ uint32_t Al[64 * SWD];

    const int tid  = threadIdx.x;
    const int wid  = tid >> 5;
    const int lane = tid & 31;
    const int g    = lane >> 2;
    const int t    = lane & 3;
    const int warp_m = wid >> 2;
    const int warp_n = wid & 3;
    const int rowbase = rbeg + blockIdx.x * 64;

    for (int i = tid; i < 64 * (K / 4); i += 256) {
        int row = i / (K / 4);
        int kq  = (i % (K / 4)) * 4;
        float4 v = make_float4(0.f, 0.f, 0.f, 0.f);
        int grow = rowbase + row;
        if (grow < rend) v = *(const float4*)(A + (size_t)grow * K + kq);
        __nv_bfloat162 h01 = __floats2bfloat162_rn(v.x, v.y);
        __nv_bfloat162 h23 = __floats2bfloat162_rn(v.z, v.w);
        __nv_bfloat162 l01 = __floats2bfloat162_rn(v.x - __bfloat162float(h01.x),
                                                   v.y - __bfloat162float(h01.y));
        __nv_bfloat162 l23 = __floats2bfloat162_rn(v.z - __bfloat162float(h23.x),
                                                   v.w - __bfloat162float(h23.y));
        int base = row * SWD + (kq >> 1);
        Ah[base]     = *(uint32_t*)&h01;
        Ah[base + 1] = *(uint32_t*)&h23;
        Al[base]     = *(uint32_t*)&l01;
        Al[base + 1] = *(uint32_t*)&l23;
    }
    __syncthreads();

    const uint32_t* BwH = (const uint32_t*)Bhi;
    const uint32_t* BwL = (const uint32_t*)Blo;

    float c[2][NF][4];
    #pragma unroll
    for (int mf = 0; mf < 2; mf++)
        #pragma unroll
        for (int nf = 0; nf < NF; nf++)
            #pragma unroll
            for (int q = 0; q < 4; q++) c[mf][nf][q] = 0.f;

    #pragma unroll
    for (int s = 0; s < 3; s++) {
        const uint32_t* Aimg = (s < 2) ? Ah : Al;
        const uint32_t* Bimg = (s == 1) ? BwL : BwH;
        #pragma unroll
        for (int ks = 0; ks < NS; ks++) {
            uint32_t a[2][4];
            #pragma unroll
            for (int mf = 0; mf < 2; mf++) {
                int r0 = warp_m * 32 + mf * 16 + g;
                int wi = r0 * SWD + ks * 8 + t;
                a[mf][0] = Aimg[wi];
                a[mf][1] = Aimg[wi + 8 * SWD];
                a[mf][2] = Aimg[wi + 4];
                a[mf][3] = Aimg[wi + 8 * SWD + 4];
            }
            #pragma unroll
            for (int nf = 0; nf < NF; nf++) {
                int n = warp_n * WN + nf * 8 + g;
                int bw = n * (K / 2) + ks * 8 + t;
                uint32_t b0 = __ldg(&Bimg[bw]);
                uint32_t b1 = __ldg(&Bimg[bw + 4]);
                #pragma unroll
                for (int mf = 0; mf < 2; mf++)
                    mma16816(c[mf][nf][0], c[mf][nf][1], c[mf][nf][2], c[mf][nf][3],
                             a[mf][0], a[mf][1], a[mf][2], a[mf][3], b0, b1);
            }
        }
    }

    #pragma unroll
    for (int nf = 0; nf < NF; nf++) {
        int col = warp_n * WN + nf * 8 + 2 * t;
        float bv0 = (col < CW1) ? b1v[col] : b2v[col - CW1];
        float bv1 = (col + 1 < CW1) ? b1v[col + 1] : b2v[col + 1 - CW1];
        #pragma unroll
        for (int mf = 0; mf < 2; mf++) {
            int row = rowbase + warp_m * 32 + mf * 16 + g;
            if (row < rend)
                *(float2*)(C + (size_t)row * CW + col) =
                    make_float2(c[mf][nf][0] + bv0, c[mf][nf][1] + bv1);
            if (row + 8 < rend)
                *(float2*)(C + (size_t)(row + 8) * CW + col) =
                    make_float2(c[mf][nf][2] + bv0, c[mf][nf][3] + bv1);
        }
    }
}

// ---------------- warp reduce ----------------
__device__ __forceinline__ float wsum(float v) {
    #pragma unroll
    for (int o = 16; o > 0; o >>= 1) v += __shfl_xor_sync(FULLM, v, o);
    return v;
}
__device__ __forceinline__ float wmax(float v) {
    #pragma unroll
    for (int o = 16; o > 0; o >>= 1) v = fmaxf(v, __shfl_xor_sync(FULLM, v, o));
    return v;
}

// ---------------- initial LayerNorm + ReLU (h -> hn), range-parameterized ----------------
__global__ void __launch_bounds__(256) ln_init_kernel(
    const float* __restrict__ h,
    const float* __restrict__ g, const float* __restrict__ b,
    float* __restrict__ hn, int nbeg, int nend)
{
    int warp = threadIdx.x >> 5;
    int lane = threadIdx.x & 31;
    int n = nbeg + blockIdx.x * 8 + warp;
    if (n >= nend) return;
    size_t base = (size_t)n * HID;

    float v0 = h[base + lane], v1 = h[base + lane + 32], v2 = h[base + lane + 64];
    float mean = wsum(v0 + v1 + v2) * (1.0f / HID);
    float d0 = v0 - mean, d1 = v1 - mean, d2 = v2 - mean;
    float rstd = rsqrtf(wsum(fmaf(d0, d0, fmaf(d1, d1, d2 * d2))) * (1.0f / HID) + 1e-5f);
    hn[base + lane]      = fmaxf(fmaf(d0 * rstd, g[lane],      b[lane]),      0.f);
    hn[base + lane + 32] = fmaxf(fmaf(d1 * rstd, g[lane + 32], b[lane + 32]), 0.f);
    hn[base + lane + 64] = fmaxf(fmaf(d2 * rstd, g[lane + 64], b[lane + 64]), 0.f);
}

// ---------------- fused GAT layer (R11 body, pass A unrolled to 4 edges) ----------------
__global__ void __launch_bounds__(256) gat_fused_kernel(
    const float* __restrict__ xlxr,
    const float* __restrict__ We,  const float* __restrict__ att,
    const float* __restrict__ bias,
    const float* __restrict__ lg,  const float* __restrict__ lb,
    int nbeg, int nend)
{
    __shared__ float sWe[HID], sAtt[HID], sBias[HID], sG[HID], sB[HID];
    int t = threadIdx.x;
    if (t < HID) {
        sWe[t] = We[t]; sAtt[t] = att[t]; sBias[t] = bias[t];
        sG[t] = lg[t];  sB[t]  = lb[t];
    }
    __syncthreads();

    int warp = t >> 5, lane = t & 31;
    int n = nbeg + blockIdx.x * 8 + warp;
    if (n >= nend) return;

    int r0 = g_rowptr[n], r1 = g_rowptr[n + 1];
    const float* xrp = xlxr + (size_t)n * 192 + 96;
    float xr0 = xrp[lane], xr1 = xrp[lane + 32], xr2 = xrp[lane + 64];
    float we0 = sWe[lane],  we1 = sWe[lane + 32],  we2 = sWe[lane + 64];
    float at0 = sAtt[lane], at1 = sAtt[lane + 32], at2 = sAtt[lane + 64];

    float m = -INFINITY, ssum = 0.f;
    float a0 = 0.f, a1 = 0.f, a2 = 0.f;

    for (int c0 = r0; c0 < r1; c0 += 32) {
        int cnt = min(32, r1 - c0);
        int p = c0 + lane;
        int   si = 0;
        float wE = 0.f;
        if (lane < cnt) {
            int2 ed = g_edge[p];
            si = ed.x;
            wE = __int_as_float(ed.y);
        }

        // ---- pass A: 4-edge unroll (4 interleaved butterflies, 12 loads in flight)
        float myal = -INFINITY;
        int j = 0;
        for (; j + 4 <= cnt; j += 4) {
            int   sa = __shfl_sync(FULLM, si, j);
            int   sb = __shfl_sync(FULLM, si, j + 1);
            int   sc = __shfl_sync(FULLM, si, j + 2);
            int   sd = __shfl_sync(FULLM, si, j + 3);
            float wa = __shfl_sync(FULLM, wE, j);
            float wb = __shfl_sync(FULLM, wE, j + 1);
            float wc = __shfl_sync(FULLM, wE, j + 2);
            float wd = __shfl_sync(FULLM, wE, j + 3);
            const float* xa = xlxr + (size_t)sa * 192;
            const float* xb = xlxr + (size_t)sb * 192;
            const float* xc = xlxr + (size_t)sc * 192;
            const float* xd = xlxr + (size_t)sd * 192;
            float xa0 = xa[lane], xa1 = xa[lane + 32], xa2 = xa[lane + 64];
            float xb0 = xb[lane], xb1 = xb[lane + 32], xb2 = xb[lane + 64];
            float xc0 = xc[lane], xc1 = xc[lane + 32], xc2 = xc[lane + 64];
            float xd0 = xd[lane], xd1 = xd[lane + 32], xd2 = xd[lane + 64];

            float e0 = xa0 + xr0 + wa * we0; e0 = e0 > 0.f ? e0 : 0.2f * e0;
            float e1 = xa1 + xr1 + wa * we1; e1 = e1 > 0.f ? e1 : 0.2f * e1;
            float e2 = xa2 + xr2 + wa * we2; e2 = e2 > 0.f ? e2 : 0.2f * e2;
            float ta = fmaf(e0, at0, fmaf(e1, at1, e2 * at2));

            float f0 = xb0 + xr0 + wb * we0; f0 = f0 > 0.f ? f0 : 0.2f * f0;
            float f1 = xb1 + xr1 + wb * we1; f1 = f1 > 0.f ? f1 : 0.2f * f1;
            float f2 = xb2 + xr2 + wb * we2; f2 = f2 > 0.f ? f2 : 0.2f * f2;
            float tb = fmaf(f0, at0, fmaf(f1, at1, f2 * at2));

            float g0 = xc0 + xr0 + wc * we0; g0 = g0 > 0.f ? g0 : 0.2f * g0;
            float g1 = xc1 + xr1 + wc * we1; g1 = g1 > 0.f ? g1 : 0.2f * g1;
            float g2 = xc2 + xr2 + wc * we2; g2 = g2 > 0.f ? g2 : 0.2f * g2;
            float tc = fmaf(g0, at0, fmaf(g1, at1, g2 * at2));

            float h0 = xd0 + xr0 + wd * we0; h0 = h0 > 0.f ? h0 : 0.2f * h0;
            float h1 = xd1 + xr1 + wd * we1; h1 = h1 > 0.f ? h1 : 0.2f * h1;
            float h2 = xd2 + xr2 + wd * we2; h2 = h2 > 0.f ? h2 : 0.2f * h2;
            float td = fmaf(h0, at0, fmaf(h1, at1, h2 * at2));

            #pragma unroll
            for (int o = 16; o > 0; o >>= 1) {
                ta += __shfl_xor_sync(FULLM, ta, o);
                tb += __shfl_xor_sync(FULLM, tb, o);
                tc += __shfl_xor_sync(FULLM, tc, o);
                td += __shfl_xor_sync(FULLM, td, o);
            }
            myal = (lane == j)     ? ta : myal;
            myal = (lane == j + 1) ? tb : myal;
            myal = (lane == j + 2) ? tc : myal;
            myal = (lane == j + 3) ? td : myal;
        }
        for (; j + 2 <= cnt; j += 2) {
            int   sa = __shfl_sync(FULLM, si, j);
            int   sb = __shfl_sync(FULLM, si, j + 1);
            float wa = __shfl_sync(FULLM, wE, j);
            float wb = __shfl_sync(FULLM, wE, j + 1);
            const float* xa = xlxr + (size_t)sa * 192;
            const float* xb = xlxr + (size_t)sb * 192;
            float xa0 = xa[lane], xa1 = xa[lane + 32], xa2 = xa[lane + 64];
            float xb0 = xb[lane], xb1 = xb[lane + 32], xb2 = xb[lane + 64];

            float e0 = xa0 + xr0 + wa * we0; e0 = e0 > 0.f ? e0 : 0.2f * e0;
            float e1 = xa1 + xr1 + wa * we1; e1 = e1 > 0.f ? e1 : 0.2f * e1;
            float e2 = xa2 + xr2 + wa * we2; e2 = e2 > 0.f ? e2 : 0.2f * e2;
            float ta = fmaf(e0, at0, fmaf(e1, at1, e2 * at2));

            float f0 = xb0 + xr0 + wb * we0; f0 = f0 > 0.f ? f0 : 0.2f * f0;
            float f1 = xb1 + xr1 + wb * we1; f1 = f1 > 0.f ? f1 : 0.2f * f1;
            float f2 = xb2 + xr2 + wb * we2; f2 = f2 > 0.f ? f2 : 0.2f * f2;
            float tb = fmaf(f0, at0, fmaf(f1, at1, f2 * at2));

            #pragma unroll
            for (int o = 16; o > 0; o >>= 1) {
                ta += __shfl_xor_sync(FULLM, ta, o);
                tb += __shfl_xor_sync(FULLM, tb, o);
            }
            myal = (lane == j)     ? ta : myal;
            myal = (lane == j + 1) ? tb : myal;
        }
        if (j < cnt) {
            int   sa = __shfl_sync(FULLM, si, j);
            float wa = __shfl_sync(FULLM, wE, j);
            const float* xa = xlxr + (size_t)sa * 192;
            float xa0 = xa[lane], xa1 = xa[lane + 32], xa2 = xa[lane + 64];
            float e0 = xa0 + xr0 + wa * we0; e0 = e0 > 0.f ? e0 : 0.2f * e0;
            float e1 = xa1 + xr1 + wa * we1; e1 = e1 > 0.f ? e1 : 0.2f * e1;
            float e2 = xa2 + xr2 + wa * we2; e2 = e2 > 0.f ? e2 : 0.2f * e2;
            float ta = fmaf(e0, at0, fmaf(e1, at1, e2 * at2));
            #pragma unroll
            for (int o = 16; o > 0; o >>= 1) ta += __shfl_xor_sync(FULLM, ta, o);
            myal = (lane == j) ? ta : myal;
        }

        // ---- chunk-level online softmax merge
        float cm = wmax(myal);
        float nm = fmaxf(m, cm);
        float corr = __expf(m - nm);
        ssum *= corr; a0 *= corr; a1 *= corr; a2 *= corr;
        float wexp = (lane < cnt) ? __expf(myal - nm) : 0.f;
        ssum += wsum(wexp);
        m = nm;

        // ---- pass B: aggregation (rows L1-hot from pass A)
        int jj = 0;
        for (; jj + 4 <= cnt; jj += 4) {
            float w0 = __shfl_sync(FULLM, wexp, jj + 0);
            float w1 = __shfl_sync(FULLM, wexp, jj + 1);
            float w2 = __shfl_sync(FULLM, wexp, jj + 2);
            float w3 = __shfl_sync(FULLM, wexp, jj + 3);
            const float* x0p = xlxr + (size_t)__shfl_sync(FULLM, si, jj + 0) * 192;
            const float* x1p = xlxr + (size_t)__shfl_sync(FULLM, si, jj + 1) * 192;
            const float* x2p = xlxr + (size_t)__shfl_sync(FULLM, si, jj + 2) * 192;
            const float* x3p = xlxr + (size_t)__shfl_sync(FULLM, si, jj + 3) * 192;
            float v00 = x0p[lane], v01 = x0p[lane + 32], v02 = x0p[lane + 64];
            float v10 = x1p[lane], v11 = x1p[lane + 32], v12 = x1p[lane + 64];
            float v20 = x2p[lane], v21 = x2p[lane + 32], v22 = x2p[lane + 64];
            float v30 = x3p[lane], v31 = x3p[lane + 32], v32 = x3p[lane + 64];
            a0 = fmaf(w0, v00, a0); a1 = fmaf(w0, v01, a1); a2 = fmaf(w0, v02, a2);
            a0 = fmaf(w1, v10, a0); a1 = fmaf(w1, v11, a1); a2 = fmaf(w1, v12, a2);
            a0 = fmaf(w2, v20, a0); a1 = fmaf(w2, v21, a1); a2 = fmaf(w2, v22, a2);
            a0 = fmaf(w3, v30, a0); a1 = fmaf(w3, v31, a1); a2 = fmaf(w3, v32, a2);
        }
        for (; jj < cnt; jj++) {
            float w = __shfl_sync(FULLM, wexp, jj);
            const float* xp = xlxr + (size_t)__shfl_sync(FULLM, si, jj) * 192;
            a0 = fmaf(w, xp[lane],      a0);
            a1 = fmaf(w, xp[lane + 32], a1);
            a2 = fmaf(w, xp[lane + 64], a2);
        }
    }

    float inv = 1.0f / (ssum + 1e-16f);
    a0 *= inv; a1 *= inv; a2 *= inv;

    // ---- residual + bias + LayerNorm + ReLU
    size_t base = (size_t)n * HID;
    float x0 = g_h[base + lane]      + a0 + sBias[lane];
    float x1 = g_h[base + lane + 32] + a1 + sBias[lane + 32];
    float x2 = g_h[base + lane + 64] + a2 + sBias[lane + 64];
    g_h[base + lane]      = x0;
    g_h[base + lane + 32] = x1;
    g_h[base + lane + 64] = x2;

    float mean = wsum(x0 + x1 + x2) * (1.0f / HID);
    float d0 = x0 - mean, d1 = x1 - mean, d2 = x2 - mean;
    float rstd = rsqrtf(wsum(fmaf(d0, d0, fmaf(d1, d1, d2 * d2))) * (1.0f / HID) + 1e-5f);
    g_hn[base + lane]      = fmaxf(fmaf(d0 * rstd, sG[lane],      sB[lane]),      0.f);
    g_hn[base + lane + 32] = fmaxf(fmaf(d1 * rstd, sG[lane + 32], sB[lane + 32]), 0.f);
    g_hn[base + lane + 64] = fmaxf(fmaf(d2 * rstd, sG[lane + 64], sB[lane + 64]), 0.f);
}

// ---------------- final FC ----------------
__global__ void __launch_bounds__(256) fc_kernel(
    const float* __restrict__ fcW, const float* __restrict__ fcb,
    float* __restrict__ out)
{
    int warp = threadIdx.x >> 5;
    int lane = threadIdx.x & 31;
    int n = blockIdx.x * 8 + warp;
    if (n >= N_NODES) return;
    size_t base = (size_t)n * HID;
    float acc = fmaf(g_hn[base + lane], fcW[lane],
                fmaf(g_hn[base + lane + 32], fcW[lane + 32],
                     g_hn[base + lane + 64] * fcW[lane + 64]));
    acc = wsum(acc);
    if (lane == 0) out[n] = acc + fcb[0];
}

// ---------------- launch ----------------
extern "C" void kernel_launch(void* const* d_in, const int* in_sizes, int n_in,
                              void* d_out, int out_size)
{
    const float* x    = (const float*)d_in[0];
    const void*  ei   = (const void*) d_in[1];
    const float* ew   = (const float*)d_in[2];
    const float* encW = (const float*)d_in[3];
    const float* encb = (const float*)d_in[4];
    const float* Wl   = (const float*)d_in[5];
    const float* bl   = (const float*)d_in[6];
    const float* Wr   = (const float*)d_in[7];
    const float* br   = (const float*)d_in[8];
    const float* We   = (const float*)d_in[9];
    const float* att  = (const float*)d_in[10];
    const float* bias = (const float*)d_in[11];
    const float* lng  = (const float*)d_in[12];
    const float* lnb  = (const float*)d_in[13];
    const float* lnfg = (const float*)d_in[14];
    const float* lnfb = (const float*)d_in[15];
    const float* fcW  = (const float*)d_in[16];
    const float* fcb  = (const float*)d_in[17];
    float*       out  = (float*)d_out;

    void *p_h, *p_hn, *p_cnt, *p_x0, *p_x1, *p_bh, *p_bl;
    cudaGetSymbolAddress(&p_h,   g_h);
    cudaGetSymbolAddress(&p_hn,  g_hn);
    cudaGetSymbolAddress(&p_cnt, g_cnt);
    cudaGetSymbolAddress(&p_x0,  g_xlxr0);
    cudaGetSymbolAddress(&p_x1,  g_xlxr1);
    cudaGetSymbolAddress(&p_bh,  g_bw_hi);
    cudaGetSymbolAddress(&p_bl,  g_bw_lo);
    float* hbuf  = (float*)p_h;
    float* hnbuf = (float*)p_hn;
    float* xbuf[2] = { (float*)p_x0, (float*)p_x1 };
    const unsigned short* bwh = (const unsigned short*)p_bh;
    const unsigned short* bwl = (const unsigned short*)p_bl;

    const int GEMM_A = NHALF / 64;
    const int GEMM_B = (N_NODES - NHALF + 63) / 64;
    const int NODE_A = NHALF / 8;
    const int NODE_B = (N_NODES - NHALF + 7) / 8;
    const int node_blocks  = (N_NODES + 7) / 8;
    const int edge2_blocks = (E_EDGES / 2 + 255) / 256;
    const int prep_blocks  = (BW_TOTAL + 255) / 256;

    cudaStream_t s2, s3;
    cudaStreamCreateWithFlags(&s2, cudaStreamNonBlocking);
    cudaStreamCreateWithFlags(&s3, cudaStreamNonBlocking);
    cudaEvent_t evFork, evCSR, evEncA, evGA[L_LAYERS], evGatA[L_LAYERS];
    cudaEventCreateWithFlags(&evFork, cudaEventDisableTiming);
    cudaEventCreateWithFlags(&evCSR,  cudaEventDisableTiming);
    cudaEventCreateWithFlags(&evEncA, cudaEventDisableTiming);
    for (int i = 0; i < L_LAYERS; i++) {
        cudaEventCreateWithFlags(&evGA[i],   cudaEventDisableTiming);
        cudaEventCreateWithFlags(&evGatA[i], cudaEventDisableTiming);
    }

    cudaEventRecord(evFork, 0);
    cudaStreamWaitEvent(s2, evFork, 0);
    cudaStreamWaitEvent(s3, evFork, 0);

    // ---- s2: CSR build ----
    detect_kernel<<<1, 1, 0, s2>>>((const int*)ei);
    cudaMemsetAsync(p_cnt, 0, N_NODES * sizeof(int), s2);
    hist_kernel<<<edge2_blocks, 256, 0, s2>>>(ei);
    scan_kernel<<<1, 1024, 0, s2>>>();
    scatter_kernel<<<edge2_blocks, 256, 0, s2>>>(ei, ew);
    cudaEventRecord(evCSR, s2);

    // ---- main: weight prep, then enc(A) ----
    prep_w_kernel<<<prep_blocks, 256>>>(encW, Wl, Wr);
    gemm_mma_kernel<F_IN, HID, HID, 24><<<GEMM_A, 256>>>(
        x, bwh + BW_ENC_OFF, bwl + BW_ENC_OFF, encb, encb, hbuf, 0, NHALF);
    cudaEventRecord(evEncA, 0);

    cudaStreamWaitEvent(s3, evEncA, 0);
    ln_init_kernel<<<NODE_A, 256, 0, s3>>>(hbuf, lng, lnb, hnbuf, 0, NHALF);
    gemm_mma_kernel<HID, 2 * HID, HID, 48><<<GEMM_A, 256, 0, s3>>>(
        hnbuf, bwh + BW_LAY_OFF, bwl + BW_LAY_OFF, bl, br, xbuf[0], 0, NHALF);
    cudaEventRecord(evGA[0], s3);

    gemm_mma_kernel<F_IN, HID, HID, 24><<<GEMM_B, 256>>>(
        x, bwh + BW_ENC_OFF, bwl + BW_ENC_OFF, encb, encb, hbuf, NHALF, N_NODES);
    ln_init_kernel<<<NODE_B, 256>>>(hbuf, lng, lnb, hnbuf, NHALF, N_NODES);
    gemm_mma_kernel<HID, 2 * HID, HID, 48><<<GEMM_B, 256>>>(
        hnbuf, bwh + BW_LAY_OFF, bwl + BW_LAY_OFF, bl, br, xbuf[0], NHALF, N_NODES);

    cudaStreamWaitEvent(0, evGA[0], 0);
    cudaStreamWaitEvent(0, evCSR, 0);

    // ---- pipelined layer loop (R10/R11 half-split topology) ----
    for (int i = 0; i < L_LAYERS; i++) {
        const float* gnext = (i < L_LAYERS - 1) ? (lng + (i + 1) * HID) : lnfg;
        const float* bnext = (i < L_LAYERS - 1) ? (lnb + (i + 1) * HID) : lnfb;
        float* xb_cur = xbuf[i & 1];

        gat_fused_kernel<<<NODE_A, 256>>>(
            xb_cur, We + i * HID, att + i * HID, bias + i * HID, gnext, bnext,
            0, NHALF);
        cudaEventRecord(evGatA[i], 0);

        if (i + 1 < L_LAYERS) {
            float* xb_nxt = xbuf[(i + 1) & 1];
            cudaStreamWaitEvent(s3, evGatA[i], 0);
            gemm_mma_kernel<HID, 2 * HID, HID, 48><<<GEMM_A, 256, 0, s3>>>(
                hnbuf, bwh + BW_LAY_OFF + (i + 1) * 18432, bwl + BW_LAY_OFF + (i + 1) * 18432,
                bl + (i + 1) * HID, br + (i + 1) * HID, xb_nxt, 0, NHALF);
            cudaEventRecord(evGA[i + 1], s3);

            gat_fused_kernel<<<NODE_B, 256>>>(
                xb_cur, We + i * HID, att + i * HID, bias + i * HID, gnext, bnext,
                NHALF, N_NODES);
            gemm_mma_kernel<HID, 2 * HID, HID, 48><<<GEMM_B, 256>>>(
                hnbuf, bwh + BW_LAY_OFF + (i + 1) * 18432, bwl + BW_LAY_OFF + (i + 1) * 18432,
                bl + (i + 1) * HID, br + (i + 1) * HID, xb_nxt, NHALF, N_NODES);
            cudaStreamWaitEvent(0, evGA[i + 1], 0);
        } else {
            gat_fused_kernel<<<NODE_B, 256>>>(
                xb_cur, We + i * HID, att + i * HID, bias + i * HID, gnext, bnext,
                NHALF, N_NODES);
        }
    }

    fc_kernel<<<node_blocks, 256>>>(fcW, fcb, out);

    cudaEventDestroy(evFork);
    cudaEventDestroy(evCSR);
    cudaEventDestroy(evEncA);
    for (int i = 0; i < L_LAYERS; i++) {
        cudaEventDestroy(evGA[i]);
        cudaEventDestroy(evGatA[i]);
    }
    cudaStreamDestroy(s2);
    cudaStreamDestroy(s3);
}

// round 15
// speedup vs baseline: 1.1813x; 1.0458x over previous
#include <cuda_runtime.h>
#include <cuda_bf16.h>
#include <cstdint>
#include <math.h>

#define N_NODES 50000
#define NHALF   25024          // multiple of 64 and 8
#define E_EDGES 800000
#define F_IN    128
#define HID     96
#define L_LAYERS 4
#define FULLM 0xffffffffu

// ---------------- device scratch ----------------
__device__ __align__(16) float g_h    [N_NODES * HID];
__device__ __align__(16) float g_hn   [N_NODES * HID];
__device__ __align__(16) float g_xlxr0[N_NODES * 2 * HID];  // ping
__device__ __align__(16) float g_xlxr1[N_NODES * 2 * HID];  // pong
__device__ __align__(16) int   g_cnt   [N_NODES];
__device__ __align__(16) int   g_rowptr[N_NODES + 1];
__device__ __align__(16) int   g_cursor[N_NODES];
__device__ __align__(16) int2  g_edge  [E_EDGES];   // (src, ew bits), sorted by dst
__device__ int g_is64;

// bf16 weight images, n-major [CW][K]: enc 96x128 @0; layer i 192x96 @ 12288 + i*18432
#define BW_ENC_OFF 0
#define BW_LAY_OFF 12288
#define BW_TOTAL   (12288 + 4 * 18432)
__device__ __align__(16) unsigned short g_bw_hi[BW_TOTAL];
__device__ __align__(16) unsigned short g_bw_lo[BW_TOTAL];

// ---------------- edge_index dtype sniff ----------------
__global__ void detect_kernel(const int* ei32) {
    bool is64 = true;
    #pragma unroll
    for (int i = 0; i < 8; i++) if (ei32[2 * i + 1] != 0) is64 = false;
    g_is64 = is64 ? 1 : 0;
}

__device__ __forceinline__ void load_edge(const void* ei, int e, int& s, int& d) {
    if (g_is64) {
        const long long* p = (const long long*)ei;
        s = (int)p[e]; d = (int)p[E_EDGES + e];
    } else {
        const int* p = (const int*)ei;
        s = p[e]; d = p[E_EDGES + e];
    }
}

// ---------------- CSR build ----------------
__global__ void __launch_bounds__(256) hist_kernel(const void* ei) {
    int base = (blockIdx.x * blockDim.x + threadIdx.x) * 2;
    #pragma unroll
    for (int i = 0; i < 2; i++) {
        int e = base + i;
        if (e < E_EDGES) {
            int s, d; load_edge(ei, e, s, d);
            atomicAdd(&g_cnt[d], 1);
        }
    }
}

__global__ void __launch_bounds__(1024) scan_kernel() {
    __shared__ int ps[1024];
    int t = threadIdx.x;
    const int CH = (N_NODES + 1023) / 1024;
    int base = t * CH;
    int sum = 0;
    for (int i = 0; i < CH; i++) {
        int idx = base + i;
        if (idx < N_NODES) sum += g_cnt[idx];
    }
    ps[t] = sum;
    __syncthreads();
    for (int off = 1; off < 1024; off <<= 1) {
        int v = (t >= off) ? ps[t - off] : 0;
        __syncthreads();
        ps[t] += v;
        __syncthreads();
    }
    int run = ps[t] - sum;
    for (int i = 0; i < CH; i++) {
        int idx = base + i;
        if (idx < N_NODES) {
            g_rowptr[idx] = run;
            g_cursor[idx] = run;
            run += g_cnt[idx];
        }
    }
    if (t == 0) g_rowptr[N_NODES] = E_EDGES;
}

__global__ void __launch_bounds__(256) scatter_kernel(const void* ei, const float* __restrict__ ew) {
    int base = (blockIdx.x * blockDim.x + threadIdx.x) * 2;
    #pragma unroll
    for (int i = 0; i < 2; i++) {
        int e = base + i;
        if (e < E_EDGES) {
            int s, d; load_edge(ei, e, s, d);
            int p = atomicAdd(&g_cursor[d], 1);
            g_edge[p] = make_int2(s, __float_as_int(ew[e]));
        }
    }
}

// ---------------- prep: transpose + bf16-split weights into n-major images ----------------
__global__ void __launch_bounds__(256) prep_w_kernel(
    const float* __restrict__ encW, const float* __restrict__ Wl, const float* __restrict__ Wr)
{
    int idx = blockIdx.x * blockDim.x + threadIdx.x;
    if (idx >= BW_TOTAL) return;
    float v; int dest;
    if (idx < 12288) {                 // enc: [96][128]
        int n = idx >> 7, k = idx & 127;
        v = encW[k * HID + n];
        dest = n * 128 + k;
    } else {
        int r = idx - 12288;
        int i = r / 18432; r -= i * 18432;
        int n = r / HID, k = r % HID;  // [192][96]
        v = (n < HID) ? Wl[(size_t)i * HID * HID + k * HID + n]
                      : Wr[(size_t)i * HID * HID + k * HID + (n - HID)];
        dest = BW_LAY_OFF + i * 18432 + n * HID + k;
    }
    __nv_bfloat16 hi = __float2bfloat16(v);
    float lof = v - __bfloat162float(hi);
    __nv_bfloat16 lo = __float2bfloat16(lof);
    g_bw_hi[dest] = *(unsigned short*)&hi;
    g_bw_lo[dest] = *(unsigned short*)&lo;
}

// ---------------- tensor-core GEMM via mma.sync (R11-proven) ----------------
__device__ __forceinline__ void mma16816(
    float& c0, float& c1, float& c2, float& c3,
    uint32_t a0, uint32_t a1, uint32_t a2, uint32_t a3,
    uint32_t b0, uint32_t b1)
{
    asm volatile(
        "mma.sync.aligned.m16n8k16.row.col.f32.bf16.bf16.f32 "
        "{%0,%1,%2,%3}, {%4,%5,%6,%7}, {%8,%9}, {%0,%1,%2,%3};"
        : "+f"(c0), "+f"(c1), "+f"(c2), "+f"(c3)
        : "r"(a0), "r"(a1), "r"(a2), "r"(a3), "r"(b0), "r"(b1));
}

template <int K, int CW, int CW1, int WN>
__global__ void __launch_bounds__(256) gemm_mma_kernel(
    const float* __restrict__ A,
    const unsigned short* __restrict__ Bhi, const unsigned short* __restrict__ Blo,
    const float* __restrict__ b1v, const float* __restrict__ b2v,
    float* __restrict__ C, int rbeg, int rend)
{
    constexpr int NS  = K / 16;
    constexpr int NF  = WN / 8;
    constexpr int SWD = K / 2 + 4;

    __shared__ uint32_t Ah[64 * SWD];
    __shared__ uint32_t Al[64 * SWD];

    const int tid  = threadIdx.x;
    const int wid  = tid >> 5;
    const int lane = tid & 31;
    const int g    = lane >> 2;
    const int t    = lane & 3;
    const int warp_m = wid >> 2;
    const int warp_n = wid & 3;
    const int rowbase = rbeg + blockIdx.x * 64;

    for (int i = tid; i < 64 * (K / 4); i += 256) {
        int row = i / (K / 4);
        int kq  = (i % (K / 4)) * 4;
        float4 v = make_float4(0.f, 0.f, 0.f, 0.f);
        int grow = rowbase + row;
        if (grow < rend) v = *(const float4*)(A + (size_t)grow * K + kq);
        __nv_bfloat162 h01 = __floats2bfloat162_rn(v.x, v.y);
        __nv_bfloat162 h23 = __floats2bfloat162_rn(v.z, v.w);
        __nv_bfloat162 l01 = __floats2bfloat162_rn(v.x - __bfloat162float(h01.x),
                                                   v.y - __bfloat162float(h01.y));
        __nv_bfloat162 l23 = __floats2bfloat162_rn(v.z - __bfloat162float(h23.x),
                                                   v.w - __bfloat162float(h23.y));
        int base = row * SWD + (kq >> 1);
        Ah[base]     = *(uint32_t*)&h01;
        Ah[base + 1] = *(uint32_t*)&h23;
        Al[base]     = *(uint32_t*)&l01;
        Al[base + 1] = *(uint32_t*)&l23;
    }
    __syncthreads();

    const uint32_t* BwH = (const uint32_t*)Bhi;
    const uint32_t* BwL = (const uint32_t*)Blo;

    float c[2][NF][4];
    #pragma unroll
    for (int mf = 0; mf < 2; mf++)
        #pragma unroll
        for (int nf = 0; nf < NF; nf++)
            #pragma unroll
            for (int q = 0; q < 4; q++) c[mf][nf][q] = 0.f;

    #pragma unroll
    for (int s = 0; s < 3; s++) {
        const uint32_t* Aimg = (s < 2) ? Ah : Al;
        const uint32_t* Bimg = (s == 1) ? BwL : BwH;
        #pragma unroll
        for (int ks = 0; ks < NS; ks++) {
            uint32_t a[2][4];
            #pragma unroll
            for (int mf = 0; mf < 2; mf++) {
                int r0 = warp_m * 32 + mf * 16 + g;
                int wi = r0 * SWD + ks * 8 + t;
                a[mf][0] = Aimg[wi];
                a[mf][1] = Aimg[wi + 8 * SWD];
                a[mf][2] = Aimg[wi + 4];
                a[mf][3] = Aimg[wi + 8 * SWD + 4];
            }
            #pragma unroll
            for (int nf = 0; nf < NF; nf++) {
                int n = warp_n * WN + nf * 8 + g;
                int bw = n * (K / 2) + ks * 8 + t;
                uint32_t b0 = __ldg(&Bimg[bw]);
                uint32_t b1 = __ldg(&Bimg[bw + 4]);
                #pragma unroll
                for (int mf = 0; mf < 2; mf++)
                    mma16816(c[mf][nf][0], c[mf][nf][1], c[mf][nf][2], c[mf][nf][3],
                             a[mf][0], a[mf][1], a[mf][2], a[mf][3], b0, b1);
            }
        }
    }

    #pragma unroll
    for (int nf = 0; nf < NF; nf++) {
        int col = warp_n * WN + nf * 8 + 2 * t;
        float bv0 = (col < CW1) ? b1v[col] : b2v[col - CW1];
        float bv1 = (col + 1 < CW1) ? b1v[col + 1] : b2v[col + 1 - CW1];
        #pragma unroll
        for (int mf = 0; mf < 2; mf++) {
            int row = rowbase + warp_m * 32 + mf * 16 + g;
            if (row < rend)
                *(float2*)(C + (size_t)row * CW + col) =
                    make_float2(c[mf][nf][0] + bv0, c[mf][nf][1] + bv1);
            if (row + 8 < rend)
                *(float2*)(C + (size_t)(row + 8) * CW + col) =
                    make_float2(c[mf][nf][2] + bv0, c[mf][nf][3] + bv1);
        }
    }
}

// ---------------- warp reduce ----------------
__device__ __forceinline__ float wsum(float v) {
    #pragma unroll
    for (int o = 16; o > 0; o >>= 1) v += __shfl_xor_sync(FULLM, v, o);
    return v;
}
__device__ __forceinline__ float wmax(float v) {
    #pragma unroll
    for (int o = 16; o > 0; o >>= 1) v = fmaxf(v, __shfl_xor_sync(FULLM, v, o));
    return v;
}

// ---------------- initial LayerNorm + ReLU (h -> hn), range-parameterized ----------------
__global__ void __launch_bounds__(256) ln_init_kernel(
    const float* __restrict__ h,
    const float* __restrict__ g, const float* __restrict__ b,
    float* __restrict__ hn, int nbeg, int nend)
{
    int warp = threadIdx.x >> 5;
    int lane = threadIdx.x & 31;
    int n = nbeg + blockIdx.x * 8 + warp;
    if (n >= nend) return;
    size_t base = (size_t)n * HID;

    float v0 = h[base + lane], v1 = h[base + lane + 32], v2 = h[base + lane + 64];
    float mean = wsum(v0 + v1 + v2) * (1.0f / HID);
    float d0 = v0 - mean, d1 = v1 - mean, d2 = v2 - mean;
    float rstd = rsqrtf(wsum(fmaf(d0, d0, fmaf(d1, d1, d2 * d2))) * (1.0f / HID) + 1e-5f);
    hn[base + lane]      = fmaxf(fmaf(d0 * rstd, g[lane],      b[lane]),      0.f);
    hn[base + lane + 32] = fmaxf(fmaf(d1 * rstd, g[lane + 32], b[lane + 32]), 0.f);
    hn[base + lane + 64] = fmaxf(fmaf(d2 * rstd, g[lane + 64], b[lane + 64]), 0.f);
}

// ---------------- fused GAT layer (R11 body, pass A software-pipelined) ----------------
// Prefetch the next 2-edge group's rows BEFORE the current group's shuffle
// butterfly, so L2 latency overlaps the ~130-cycle shuffle dependency chain.
__global__ void __launch_bounds__(256) gat_fused_kernel(
    const float* __restrict__ xlxr,
    const float* __restrict__ We,  const float* __restrict__ att,
    const float* __restrict__ bias,
    const float* __restrict__ lg,  const float* __restrict__ lb,
    int nbeg, int nend)
{
    __shared__ float sWe[HID], sAtt[HID], sBias[HID], sG[HID], sB[HID];
    int t = threadIdx.x;
    if (t < HID) {
        sWe[t] = We[t]; sAtt[t] = att[t]; sBias[t] = bias[t];
        sG[t] = lg[t];  sB[t]  = lb[t];
    }
    __syncthreads();

    int warp = t >> 5, lane = t & 31;
    int n = nbeg + blockIdx.x * 8 + warp;
    if (n >= nend) return;

    int r0 = g_rowptr[n], r1 = g_rowptr[n + 1];
    const float* xrp = xlxr + (size_t)n * 192 + 96;
    float xr0 = xrp[lane], xr1 = xrp[lane + 32], xr2 = xrp[lane + 64];
    float we0 = sWe[lane],  we1 = sWe[lane + 32],  we2 = sWe[lane + 64];
    float at0 = sAtt[lane], at1 = sAtt[lane + 32], at2 = sAtt[lane + 64];

    float m = -INFINITY, ssum = 0.f;
    float a0 = 0.f, a1 = 0.f, a2 = 0.f;

    for (int c0 = r0; c0 < r1; c0 += 32) {
        int cnt = min(32, r1 - c0);
        int p = c0 + lane;
        int   si = 0;
        float wE = 0.f;
        if (lane < cnt) {
            int2 ed = g_edge[p];
            si = ed.x;
            wE = __int_as_float(ed.y);
        }

        // ---- pass A: 2-edge groups, software-pipelined prefetch ----
        float myal = -INFINITY;
        float pa0 = 0.f, pa1 = 0.f, pa2 = 0.f, pwa = 0.f;
        float pb0 = 0.f, pb1 = 0.f, pb2 = 0.f, pwb = 0.f;
        if (cnt >= 2) {
            int sa = __shfl_sync(FULLM, si, 0);
            int sb = __shfl_sync(FULLM, si, 1);
            pwa = __shfl_sync(FULLM, wE, 0);
            pwb = __shfl_sync(FULLM, wE, 1);
            const float* xa = xlxr + (size_t)sa * 192;
            const float* xb = xlxr + (size_t)sb * 192;
            pa0 = xa[lane]; pa1 = xa[lane + 32]; pa2 = xa[lane + 64];
            pb0 = xb[lane]; pb1 = xb[lane + 32]; pb2 = xb[lane + 64];
        }
        int j = 0;
        for (; j + 2 <= cnt; j += 2) {
            // compute from prefetched registers
            float e0 = pa0 + xr0 + pwa * we0; e0 = e0 > 0.f ? e0 : 0.2f * e0;
            float e1 = pa1 + xr1 + pwa * we1; e1 = e1 > 0.f ? e1 : 0.2f * e1;
            float e2 = pa2 + xr2 + pwa * we2; e2 = e2 > 0.f ? e2 : 0.2f * e2;
            float ta = fmaf(e0, at0, fmaf(e1, at1, e2 * at2));

            float f0 = pb0 + xr0 + pwb * we0; f0 = f0 > 0.f ? f0 : 0.2f * f0;
            float f1 = pb1 + xr1 + pwb * we1; f1 = f1 > 0.f ? f1 : 0.2f * f1;
            float f2 = pb2 + xr2 + pwb * we2; f2 = f2 > 0.f ? f2 : 0.2f * f2;
            float tb = fmaf(f0, at0, fmaf(f1, at1, f2 * at2));

            // prefetch next group BEFORE the butterfly (overlaps shfl chain)
            int jn = j + 2;
            if (jn + 2 <= cnt) {
                int sa = __shfl_sync(FULLM, si, jn);
                int sb = __shfl_sync(FULLM, si, jn + 1);
                pwa = __shfl_sync(FULLM, wE, jn);
                pwb = __shfl_sync(FULLM, wE, jn + 1);
                const float* xa = xlxr + (size_t)sa * 192;
                const float* xb = xlxr + (size_t)sb * 192;
                pa0 = xa[lane]; pa1 = xa[lane + 32]; pa2 = xa[lane + 64];
                pb0 = xb[lane]; pb1 = xb[lane + 32]; pb2 = xb[lane + 64];
            }

            #pragma unroll
            for (int o = 16; o > 0; o >>= 1) {
                ta += __shfl_xor_sync(FULLM, ta, o);
                tb += __shfl_xor_sync(FULLM, tb, o);
            }
            myal = (lane == j)     ? ta : myal;
            myal = (lane == j + 1) ? tb : myal;
        }
        if (j < cnt) {
            int   sa = __shfl_sync(FULLM, si, j);
            float wa = __shfl_sync(FULLM, wE, j);
            const float* xa = xlxr + (size_t)sa * 192;
            float xa0 = xa[lane], xa1 = xa[lane + 32], xa2 = xa[lane + 64];
            float e0 = xa0 + xr0 + wa * we0; e0 = e0 > 0.f ? e0 : 0.2f * e0;
            float e1 = xa1 + xr1 + wa * we1; e1 = e1 > 0.f ? e1 : 0.2f * e1;
            float e2 = xa2 + xr2 + wa * we2; e2 = e2 > 0.f ? e2 : 0.2f * e2;
            float ta = fmaf(e0, at0, fmaf(e1, at1, e2 * at2));
            #pragma unroll
            for (int o = 16; o > 0; o >>= 1) ta += __shfl_xor_sync(FULLM, ta, o);
            myal = (lane == j) ? ta : myal;
        }

        // ---- chunk-level online softmax merge
        float cm = wmax(myal);
        float nm = fmaxf(m, cm);
        float corr = __expf(m - nm);
        ssum *= corr; a0 *= corr; a1 *= corr; a2 *= corr;
        float wexp = (lane < cnt) ? __expf(myal - nm) : 0.f;
        ssum += wsum(wexp);
        m = nm;

        // ---- pass B: aggregation (rows L1-hot from pass A)
        int jj = 0;
        for (; jj + 4 <= cnt; jj += 4) {
            float w0 = __shfl_sync(FULLM, wexp, jj + 0);
            float w1 = __shfl_sync(FULLM, wexp, jj + 1);
            float w2 = __shfl_sync(FULLM, wexp, jj + 2);
            float w3 = __shfl_sync(FULLM, wexp, jj + 3);
            const float* x0p = xlxr + (size_t)__shfl_sync(FULLM, si, jj + 0) * 192;
            const float* x1p = xlxr + (size_t)__shfl_sync(FULLM, si, jj + 1) * 192;
            const float* x2p = xlxr + (size_t)__shfl_sync(FULLM, si, jj + 2) * 192;
            const float* x3p = xlxr + (size_t)__shfl_sync(FULLM, si, jj + 3) * 192;
            float v00 = x0p[lane], v01 = x0p[lane + 32], v02 = x0p[lane + 64];
            float v10 = x1p[lane], v11 = x1p[lane + 32], v12 = x1p[lane + 64];
            float v20 = x2p[lane], v21 = x2p[lane + 32], v22 = x2p[lane + 64];
            float v30 = x3p[lane], v31 = x3p[lane + 32], v32 = x3p[lane + 64];
            a0 = fmaf(w0, v00, a0); a1 = fmaf(w0, v01, a1); a2 = fmaf(w0, v02, a2);
            a0 = fmaf(w1, v10, a0); a1 = fmaf(w1, v11, a1); a2 = fmaf(w1, v12, a2);
            a0 = fmaf(w2, v20, a0); a1 = fmaf(w2, v21, a1); a2 = fmaf(w2, v22, a2);
            a0 = fmaf(w3, v30, a0); a1 = fmaf(w3, v31, a1); a2 = fmaf(w3, v32, a2);
        }
        for (; jj < cnt; jj++) {
            float w = __shfl_sync(FULLM, wexp, jj);
            const float* xp = xlxr + (size_t)__shfl_sync(FULLM, si, jj) * 192;
            a0 = fmaf(w, xp[lane],      a0);
            a1 = fmaf(w, xp[lane + 32], a1);
            a2 = fmaf(w, xp[lane + 64], a2);
        }
    }

    float inv = 1.0f / (ssum + 1e-16f);
    a0 *= inv; a1 *= inv; a2 *= inv;

    // ---- residual + bias + LayerNorm + ReLU
    size_t base = (size_t)n * HID;
    float x0 = g_h[base + lane]      + a0 + sBias[lane];
    float x1 = g_h[base + lane + 32] + a1 + sBias[lane + 32];
    float x2 = g_h[base + lane + 64] + a2 + sBias[lane + 64];
    g_h[base + lane]      = x0;
    g_h[base + lane + 32] = x1;
    g_h[base + lane + 64] = x2;

    float mean = wsum(x0 + x1 + x2) * (1.0f / HID);
    float d0 = x0 - mean, d1 = x1 - mean, d2 = x2 - mean;
    float rstd = rsqrtf(wsum(fmaf(d0, d0, fmaf(d1, d1, d2 * d2))) * (1.0f / HID) + 1e-5f);
    g_hn[base + lane]      = fmaxf(fmaf(d0 * rstd, sG[lane],      sB[lane]),      0.f);
    g_hn[base + lane + 32] = fmaxf(fmaf(d1 * rstd, sG[lane + 32], sB[lane + 32]), 0.f);
    g_hn[base + lane + 64] = fmaxf(fmaf(d2 * rstd, sG[lane + 64], sB[lane + 64]), 0.f);
}

// ---------------- final FC ----------------
__global__ void __launch_bounds__(256) fc_kernel(
    const float* __restrict__ fcW, const float* __restrict__ fcb,
    float* __restrict__ out)
{
    int warp = threadIdx.x >> 5;
    int lane = threadIdx.x & 31;
    int n = blockIdx.x * 8 + warp;
    if (n >= N_NODES) return;
    size_t base = (size_t)n * HID;
    float acc = fmaf(g_hn[base + lane], fcW[lane],
                fmaf(g_hn[base + lane + 32], fcW[lane + 32],
                     g_hn[base + lane + 64] * fcW[lane + 64]));
    acc = wsum(acc);
    if (lane == 0) out[n] = acc + fcb[0];
}

// ---------------- launch ----------------
extern "C" void kernel_launch(void* const* d_in, const int* in_sizes, int n_in,
                              void* d_out, int out_size)
{
    const float* x    = (const float*)d_in[0];
    const void*  ei   = (const void*) d_in[1];
    const float* ew   = (const float*)d_in[2];
    const float* encW = (const float*)d_in[3];
    const float* encb = (const float*)d_in[4];
    const float* Wl   = (const float*)d_in[5];
    const float* bl   = (const float*)d_in[6];
    const float* Wr   = (const float*)d_in[7];
    const float* br   = (const float*)d_in[8];
    const float* We   = (const float*)d_in[9];
    const float* att  = (const float*)d_in[10];
    const float* bias = (const float*)d_in[11];
    const float* lng  = (const float*)d_in[12];
    const float* lnb  = (const float*)d_in[13];
    const float* lnfg = (const float*)d_in[14];
    const float* lnfb = (const float*)d_in[15];
    const float* fcW  = (const float*)d_in[16];
    const float* fcb  = (const float*)d_in[17];
    float*       out  = (float*)d_out;

    void *p_h, *p_hn, *p_cnt, *p_x0, *p_x1, *p_bh, *p_bl;
    cudaGetSymbolAddress(&p_h,   g_h);
    cudaGetSymbolAddress(&p_hn,  g_hn);
    cudaGetSymbolAddress(&p_cnt, g_cnt);
    cudaGetSymbolAddress(&p_x0,  g_xlxr0);
    cudaGetSymbolAddress(&p_x1,  g_xlxr1);
    cudaGetSymbolAddress(&p_bh,  g_bw_hi);
    cudaGetSymbolAddress(&p_bl,  g_bw_lo);
    float* hbuf  = (float*)p_h;
    float* hnbuf = (float*)p_hn;
    float* xbuf[2] = { (float*)p_x0, (float*)p_x1 };
    const unsigned short* bwh = (const unsigned short*)p_bh;
    const unsigned short* bwl = (const unsigned short*)p_bl;

    const int GEMM_A = NHALF / 64;
    const int GEMM_B = (N_NODES - NHALF + 63) / 64;
    const int NODE_A = NHALF / 8;
    const int NODE_B = (N_NODES - NHALF + 7) / 8;
    const int node_blocks  = (N_NODES + 7) / 8;
    const int edge2_blocks = (E_EDGES / 2 + 255) / 256;
    const int prep_blocks  = (BW_TOTAL + 255) / 256;

    cudaStream_t s2, s3;
    cudaStreamCreateWithFlags(&s2, cudaStreamNonBlocking);
    cudaStreamCreateWithFlags(&s3, cudaStreamNonBlocking);
    cudaEvent_t evFork, evCSR, evEncA, evGA[L_LAYERS], evGatA[L_LAYERS];
    cudaEventCreateWithFlags(&evFork, cudaEventDisableTiming);
    cudaEventCreateWithFlags(&evCSR,  cudaEventDisableTiming);
    cudaEventCreateWithFlags(&evEncA, cudaEventDisableTiming);
    for (int i = 0; i < L_LAYERS; i++) {
        cudaEventCreateWithFlags(&evGA[i],   cudaEventDisableTiming);
        cudaEventCreateWithFlags(&evGatA[i], cudaEventDisableTiming);
    }

    cudaEventRecord(evFork, 0);
    cudaStreamWaitEvent(s2, evFork, 0);
    cudaStreamWaitEvent(s3, evFork, 0);

    // ---- s2: CSR build ----
    detect_kernel<<<1, 1, 0, s2>>>((const int*)ei);
    cudaMemsetAsync(p_cnt, 0, N_NODES * sizeof(int), s2);
    hist_kernel<<<edge2_blocks, 256, 0, s2>>>(ei);
    scan_kernel<<<1, 1024, 0, s2>>>();
    scatter_kernel<<<edge2_blocks, 256, 0, s2>>>(ei, ew);
    cudaEventRecord(evCSR, s2);

    // ---- main: weight prep, then enc(A) ----
    prep_w_kernel<<<prep_blocks, 256>>>(encW, Wl, Wr);
    gemm_mma_kernel<F_IN, HID, HID, 24><<<GEMM_A, 256>>>(
        x, bwh + BW_ENC_OFF, bwl + BW_ENC_OFF, encb, encb, hbuf, 0, NHALF);
    cudaEventRecord(evEncA, 0);

    cudaStreamWaitEvent(s3, evEncA, 0);
    ln_init_kernel<<<NODE_A, 256, 0, s3>>>(hbuf, lng, lnb, hnbuf, 0, NHALF);
    gemm_mma_kernel<HID, 2 * HID, HID, 48><<<GEMM_A, 256, 0, s3>>>(
        hnbuf, bwh + BW_LAY_OFF, bwl + BW_LAY_OFF, bl, br, xbuf[0], 0, NHALF);
    cudaEventRecord(evGA[0], s3);

    gemm_mma_kernel<F_IN, HID, HID, 24><<<GEMM_B, 256>>>(
        x, bwh + BW_ENC_OFF, bwl + BW_ENC_OFF, encb, encb, hbuf, NHALF, N_NODES);
    ln_init_kernel<<<NODE_B, 256>>>(hbuf, lng, lnb, hnbuf, NHALF, N_NODES);
    gemm_mma_kernel<HID, 2 * HID, HID, 48><<<GEMM_B, 256>>>(
        hnbuf, bwh + BW_LAY_OFF, bwl + BW_LAY_OFF, bl, br, xbuf[0], NHALF, N_NODES);

    cudaStreamWaitEvent(0, evGA[0], 0);
    cudaStreamWaitEvent(0, evCSR, 0);

    // ---- pipelined layer loop (R10/R11 half-split topology) ----
    for (int i = 0; i < L_LAYERS; i++) {
        const float* gnext = (i < L_LAYERS - 1) ? (lng + (i + 1) * HID) : lnfg;
        const float* bnext = (i < L_LAYERS - 1) ? (lnb + (i + 1) * HID) : lnfb;
        float* xb_cur = xbuf[i & 1];

        gat_fused_kernel<<<NODE_A, 256>>>(
            xb_cur, We + i * HID, att + i * HID, bias + i * HID, gnext, bnext,
            0, NHALF);
        cudaEventRecord(evGatA[i], 0);

        if (i + 1 < L_LAYERS) {
            float* xb_nxt = xbuf[(i + 1) & 1];
            cudaStreamWaitEvent(s3, evGatA[i], 0);
            gemm_mma_kernel<HID, 2 * HID, HID, 48><<<GEMM_A, 256, 0, s3>>>(
                hnbuf, bwh + BW_LAY_OFF + (i + 1) * 18432, bwl + BW_LAY_OFF + (i + 1) * 18432,
                bl + (i + 1) * HID, br + (i + 1) * HID, xb_nxt, 0, NHALF);
            cudaEventRecord(evGA[i + 1], s3);

            gat_fused_kernel<<<NODE_B, 256>>>(
                xb_cur, We + i * HID, att + i * HID, bias + i * HID, gnext, bnext,
                NHALF, N_NODES);
            gemm_mma_kernel<HID, 2 * HID, HID, 48><<<GEMM_B, 256>>>(
                hnbuf, bwh + BW_LAY_OFF + (i + 1) * 18432, bwl + BW_LAY_OFF + (i + 1) * 18432,
                bl + (i + 1) * HID, br + (i + 1) * HID, xb_nxt, NHALF, N_NODES);
            cudaStreamWaitEvent(0, evGA[i + 1], 0);
        } else {
            gat_fused_kernel<<<NODE_B, 256>>>(
                xb_cur, We + i * HID, att + i * HID, bias + i * HID, gnext, bnext,
                NHALF, N_NODES);
        }
    }

    fc_kernel<<<node_blocks, 256>>>(fcW, fcb, out);

    cudaEventDestroy(evFork);
    cudaEventDestroy(evCSR);
    cudaEventDestroy(evEncA);
    for (int i = 0; i < L_LAYERS; i++) {
        cudaEventDestroy(evGA[i]);
        cudaEventDestroy(evGatA[i]);
    }
    cudaStreamDestroy(s2);
    cudaStreamDestroy(s3);
}